// round 16
// baseline (speedup 1.0000x reference)
#include <cuda_runtime.h>
#include <cuda_fp16.h>
#include <cstdint>
#include <math.h>

// Problem constants
#define BATCH   4
#define SEQ     2048
#define EMBD    1024
#define NHEAD   16
#define HDIM    64
#define MROWS   (BATCH * SEQ)        // 8192
#define QKV_N   (3 * EMBD)           // 3072

// ---------------------------------------------------------------------------
// Scratch (device globals: allocation-free per harness rules)
// ---------------------------------------------------------------------------
__device__ __half g_a2 [(size_t)MROWS * EMBD];  // [8192,1024] fp16 (x, then attn-out)
__device__ __half g_w2a[(size_t)QKV_N * EMBD];  // [3072,1024] fp16 W_attn^T
__device__ __half g_w2p[(size_t)EMBD * EMBD];   // [1024,1024] fp16 W_proj^T
// attention operands, head-major (plain fp16)
__device__ __half g_Qp[(size_t)BATCH * NHEAD * SEQ * 64];
__device__ __half g_Kp[(size_t)BATCH * NHEAD * SEQ * 64];
__device__ __half g_Vh[(size_t)BATCH * NHEAD * SEQ * 64];

// ---------------------------------------------------------------------------
// Portable PTX helpers (valid on compute_103)
// ---------------------------------------------------------------------------
__device__ __forceinline__ uint32_t smem_u32(const void* p) {
    uint32_t a;
    asm("{ .reg .u64 t; cvta.to.shared.u64 t, %1; cvt.u32.u64 %0, t; }"
        : "=r"(a) : "l"(p));
    return a;
}
__device__ __forceinline__ void cp_async16(uint32_t dst, const void* src) {
    asm volatile("cp.async.cg.shared.global [%0], [%1], 16;"
                 :: "r"(dst), "l"(src) : "memory");
}
__device__ __forceinline__ void cp_commit() {
    asm volatile("cp.async.commit_group;" ::: "memory");
}
template <int N>
__device__ __forceinline__ void cp_wait() {
    asm volatile("cp.async.wait_group %0;" :: "n"(N) : "memory");
}
__device__ __forceinline__ void ldmatrix_x4(uint32_t* r, uint32_t addr) {
    asm volatile("ldmatrix.sync.aligned.m8n8.x4.shared.b16 {%0,%1,%2,%3}, [%4];"
                 : "=r"(r[0]), "=r"(r[1]), "=r"(r[2]), "=r"(r[3]) : "r"(addr));
}
__device__ __forceinline__ void ldmatrix_x4t(uint32_t* r, uint32_t addr) {
    asm volatile("ldmatrix.sync.aligned.m8n8.x4.trans.shared.b16 {%0,%1,%2,%3}, [%4];"
                 : "=r"(r[0]), "=r"(r[1]), "=r"(r[2]), "=r"(r[3]) : "r"(addr));
}
__device__ __forceinline__ void mma16816h(float* c, const uint32_t* a, const uint32_t* b) {
    asm volatile(
        "mma.sync.aligned.m16n8k16.row.col.f32.f16.f16.f32 "
        "{%0,%1,%2,%3}, {%4,%5,%6,%7}, {%8,%9}, {%0,%1,%2,%3};"
        : "+f"(c[0]), "+f"(c[1]), "+f"(c[2]), "+f"(c[3])
        : "r"(a[0]), "r"(a[1]), "r"(a[2]), "r"(a[3]), "r"(b[0]), "r"(b[1]));
}
__device__ __forceinline__ float ex2f(float x) {
    float r;
    asm("ex2.approx.f32 %0, %1;" : "=f"(r) : "f"(x));
    return r;
}

// ---------------------------------------------------------------------------
// Fused pack kernel (single launch):
//   blocks [0, 8192)          : x fp32 -> a2 fp16
//   blocks [8192, 11264)      : W_attn^T pack (96 x 32 tiles)
//   blocks [11264, 12288)     : W_proj^T pack (32 x 32 tiles)
// ---------------------------------------------------------------------------
__global__ __launch_bounds__(256)
void pack_all(const float* __restrict__ x, __half* __restrict__ a2,
              const float* __restrict__ Wa, __half* __restrict__ w2a,
              const float* __restrict__ Wp, __half* __restrict__ w2p)
{
    const int bid = blockIdx.x;
    if (bid < 8192) {
        const int i = bid * 256 + threadIdx.x;
        float4 v = ((const float4*)x)[i];
        __half2* d = (__half2*)a2;
        d[2 * i + 0] = __floats2half2_rn(v.x, v.y);
        d[2 * i + 1] = __floats2half2_rn(v.z, v.w);
        return;
    }
    __shared__ float t[32][33];
    const float* W;
    __half* W2;
    int n0, k0, Nd;
    if (bid < 8192 + 3072) {
        const int tb = bid - 8192;
        W = Wa; W2 = w2a; Nd = QKV_N;
        n0 = (tb % 96) * 32; k0 = (tb / 96) * 32;
    } else {
        const int tb = bid - 11264;
        W = Wp; W2 = w2p; Nd = EMBD;
        n0 = (tb % 32) * 32; k0 = (tb / 32) * 32;
    }
    const int tx = threadIdx.x & 31;
    const int ty = threadIdx.x >> 5;
    #pragma unroll
    for (int i = 0; i < 32; i += 8)
        t[ty + i][tx] = W[(size_t)(k0 + ty + i) * Nd + n0 + tx];
    __syncthreads();
    #pragma unroll
    for (int i = 0; i < 32; i += 8)
        W2[(size_t)(n0 + ty + i) * EMBD + k0 + tx] = __float2half_rn(t[tx][ty + i]);
}

// ---------------------------------------------------------------------------
// fp16 tensor-core GEMM (exact R12 config — best measured).
// ---------------------------------------------------------------------------
#define STAGE_SZ     32768               // A 16KB + B 16KB
#define GEMM_SMEM_SZ (3 * STAGE_SZ)      // 98304

__device__ __forceinline__ void load_stage(uint32_t st,
                                           const __half* A, const __half* B,
                                           int bm, int bn, int kc, int tid)
{
    const size_t ko = (size_t)kc * 64;
    const uint32_t sA = st, sB = st + 16384;
    #pragma unroll
    for (int i = 0; i < 4; i++) {
        const int idx = tid + i * 256;
        const int r = idx >> 3;
        const int g = idx & 7;
        const uint32_t so = (uint32_t)r * 128 + (uint32_t)((g ^ (r & 7)) << 4);
        cp_async16(sA + so, (const char*)(A + (size_t)(bm + r) * EMBD + ko) + g * 16);
        cp_async16(sB + so, (const char*)(B + (size_t)(bn + r) * EMBD + ko) + g * 16);
    }
}

template <int MODE>
__global__ __launch_bounds__(256, 2)
void gemm_fp16(const __half* __restrict__ A2, const __half* __restrict__ W2,
               const float* __restrict__ bias, float* __restrict__ C, int N,
               __half2* __restrict__ Qp, __half2* __restrict__ Kp,
               __half2* __restrict__ Vh)
{
    extern __shared__ char dsm[];
    const int tid  = threadIdx.x;
    const int lane = tid & 31;
    const int wid  = tid >> 5;
    const int wm   = wid >> 2;
    const int wn   = wid & 3;
    const int bm   = blockIdx.y * 128;
    const int bn   = blockIdx.x * 128;

    const uint32_t sbase = smem_u32(dsm);
    float acc[4][4][4];
    #pragma unroll
    for (int mt = 0; mt < 4; mt++)
        #pragma unroll
        for (int nt = 0; nt < 4; nt++)
            #pragma unroll
            for (int j = 0; j < 4; j++) acc[mt][nt][j] = 0.f;

    const int NK = EMBD / 64;   // 16

    load_stage(sbase,            A2, W2, bm, bn, 0, tid);
    cp_commit();
    load_stage(sbase + STAGE_SZ, A2, W2, bm, bn, 1, tid);
    cp_commit();

    uint32_t stage = 0;
    for (int kc = 0; kc < NK; kc++) {
        if (kc == NK - 1) cp_wait<0>(); else cp_wait<1>();
        __syncthreads();
        if (kc + 2 < NK) {
            uint32_t nb = stage + 2;
            if (nb >= 3) nb -= 3;
            load_stage(sbase + nb * STAGE_SZ, A2, W2, bm, bn, kc + 2, tid);
            cp_commit();
        }

        const uint32_t sA = sbase + stage * STAGE_SZ;
        const uint32_t sB = sA + 16384;
        if (++stage == 3) stage = 0;

        #pragma unroll
        for (int ks = 0; ks < 4; ks++) {
            uint32_t a[4][4], bb[2][4];
            #pragma unroll
            for (int mt = 0; mt < 4; mt++) {
                const int r = wm * 64 + mt * 16 + (lane & 15);
                const int g = ks * 2 + (lane >> 4);
                ldmatrix_x4(a[mt], sA + r * 128 + ((g ^ (r & 7)) << 4));
            }
            #pragma unroll
            for (int pp = 0; pp < 2; pp++) {
                const int n = wn * 32 + pp * 16 + ((lane >> 4) << 3) + (lane & 7);
                const int g = ks * 2 + ((lane >> 3) & 1);
                ldmatrix_x4(bb[pp], sB + n * 128 + ((g ^ (n & 7)) << 4));
            }
            #pragma unroll
            for (int mt = 0; mt < 4; mt++) {
                mma16816h(acc[mt][0], a[mt], bb[0] + 0);
                mma16816h(acc[mt][1], a[mt], bb[0] + 2);
                mma16816h(acc[mt][2], a[mt], bb[1] + 0);
                mma16816h(acc[mt][3], a[mt], bb[1] + 2);
            }
        }
    }
    __syncthreads();

    #pragma unroll
    for (int mt = 0; mt < 4; mt++) {
        const int r0 = bm + wm * 64 + mt * 16 + (lane >> 2);
        #pragma unroll
        for (int nt = 0; nt < 4; nt++) {
            const int c0 = bn + wn * 32 + nt * 8 + 2 * (lane & 3);
            const float b0 = bias[c0], b1 = bias[c0 + 1];
            float2 v0 = make_float2(acc[mt][nt][0] + b0, acc[mt][nt][1] + b1);
            float2 v1 = make_float2(acc[mt][nt][2] + b0, acc[mt][nt][3] + b1);
            if (MODE == 0) {
                *(float2*)&C[(size_t)r0 * N + c0]       = v0;
                *(float2*)&C[(size_t)(r0 + 8) * N + c0] = v1;
            } else {
                #pragma unroll
                for (int half_row = 0; half_row < 2; half_row++) {
                    const int row = r0 + half_row * 8;
                    const float2 v = half_row ? v1 : v0;
                    const int bb2 = row >> 11;
                    const int t   = row & 2047;
                    const int reg = c0 >> 10;        // 0=q 1=k 2=v
                    const int cc  = c0 & 1023;
                    const int h   = cc >> 6;
                    const int d2  = (cc & 63) >> 1;
                    const size_t ob = ((size_t)(bb2 * NHEAD + h) * SEQ + t);
                    const __half2 hv = __floats2half2_rn(v.x, v.y);
                    if (reg == 0)      Qp[ob * 32 + d2] = hv;
                    else if (reg == 1) Kp[ob * 32 + d2] = hv;
                    else               Vh[ob * 32 + d2] = hv;
                }
            }
        }
    }
}

// ---------------------------------------------------------------------------
// Tensor-core causal flash attention (plain fp16 Q/K/V).
// 8 warps x 16 rows, 128-KEY load tiles processed as two 64-key halves.
// 2-stage KV ring, ONE barrier per 128-key tile. NEW in R16: Q MMA fragments
// hoisted into registers once (loop-invariant) — no Q LDSM in the main loop.
// SMEM: Q [128][128B] + 2 x (K 16KB + V 16KB) = 80KB -> 2 CTAs/SM.
// ---------------------------------------------------------------------------
#define KV_STAGE 32768                    // K 16KB + V 16KB (128 rows each)
#define ATT_SMEM (16384 + 2 * KV_STAGE)   // 81920
#define CEXP 0.18033688f   // 0.125 * log2(e)

__global__ __launch_bounds__(256, 2)
void flash_attn_tc(const __half* __restrict__ Qp, const __half* __restrict__ Kpp,
                   const __half* __restrict__ Vh, __half* __restrict__ a2out)
{
    extern __shared__ char dsm[];
    const uint32_t sQ  = smem_u32(dsm);
    const uint32_t sKV = sQ + 16384;

    const int qt   = 15 - blockIdx.x;      // heavy tiles first
    const int bh   = blockIdx.y;
    const int b    = bh >> 4;
    const int h    = bh & 15;
    const int tid  = threadIdx.x;
    const int lane = tid & 31;
    const int w    = tid >> 5;
    const int qr0  = qt * 128;

    const __half* Kg  = Kpp + (size_t)bh * SEQ * 64;
    const __half* VhG = Vh  + (size_t)bh * SEQ * 64;

    // ---- load Q tile: 128 rows x 128B ---- (group 0)
    const __half* Qg = Qp + ((size_t)bh * SEQ + qr0) * 64;
    #pragma unroll
    for (int i = 0; i < 4; i++) {
        const int idx = tid + i * 256;     // 0..1023
        const int r = idx >> 3;
        const int g = idx & 7;
        const uint32_t sw = (uint32_t)((g ^ (r & 7)) << 4);
        cp_async16(sQ + r * 128 + sw, Qg + (size_t)r * 64 + g * 8);
    }
    cp_commit();

    // 128-key tile loader (K and V, 128 rows x 128B each)
    auto load_kv = [&](int s, int kt) {
        const __half* kg  = Kg  + (size_t)(kt * 128) * 64;
        const __half* vhg = VhG + (size_t)(kt * 128) * 64;
        const uint32_t sK  = sKV + (uint32_t)s * KV_STAGE;
        const uint32_t sV  = sK + 16384;
        #pragma unroll
        for (int i = 0; i < 4; i++) {
            const int f = tid + i * 256;   // 0..1023
            const int r = f >> 3;
            const int g = f & 7;
            const uint32_t sw = (uint32_t)((g ^ (r & 7)) << 4);
            cp_async16(sK + r * 128 + sw, kg  + (size_t)r * 64 + g * 8);
            cp_async16(sV + r * 128 + sw, vhg + (size_t)r * 64 + g * 8);
        }
    };

    const int nkt = qt + 1;                // 128-key tiles

    load_kv(0, 0);
    cp_commit();

    float O[8][4];
    #pragma unroll
    for (int j = 0; j < 8; j++)
        #pragma unroll
        for (int i = 0; i < 4; i++) O[j][i] = 0.f;
    float m0 = -1e30f, m1 = -1e30f, l0 = 0.f, l1 = 0.f;

    uint32_t qf[4][4];   // hoisted Q fragments (loop-invariant)

    const int wrow = qr0 + w * 16;
    const int kt_max_w = (wrow + 15) >> 6;   // in 64-key units

    int stage = 0;
    for (int kt = 0; kt < nkt; kt++) {
        cp_wait<0>();      // tile kt (and Q on kt==0) fully in smem
        __syncthreads();   // all warps finished compute of tile kt-1

        if (kt == 0) {
            // Q now resident: load all Q fragments once
            #pragma unroll
            for (int ks = 0; ks < 4; ks++) {
                const int r = w * 16 + (lane & 15);
                const int g = 2 * ks + (lane >> 4);
                ldmatrix_x4(qf[ks], sQ + r * 128 + ((uint32_t)(g ^ (r & 7)) << 4));
            }
        }

        // prefetch tile kt+1 into the stage drained at kt-1 (safe post-barrier)
        if (kt + 1 < nkt) {
            load_kv(stage ^ 1, kt + 1);
            cp_commit();
        }

        // two 64-key halves within the 128-key tile
        #pragma unroll
        for (int hv2 = 0; hv2 < 2; hv2++) {
            const int j64 = 2 * kt + hv2;       // 64-key tile index
            if (j64 > kt_max_w) break;
            const uint32_t sK  = sKV + (uint32_t)stage * KV_STAGE + hv2 * 8192;
            const uint32_t sVh = sKV + (uint32_t)stage * KV_STAGE + 16384 + hv2 * 8192;

            // ---- S = Q.K^T ----
            float S[8][4];
            #pragma unroll
            for (int j = 0; j < 8; j++)
                #pragma unroll
                for (int i = 0; i < 4; i++) S[j][i] = 0.f;

            #pragma unroll
            for (int ks = 0; ks < 4; ks++) {
                #pragma unroll
                for (int pp = 0; pp < 4; pp++) {
                    uint32_t kb[4];
                    const int n = pp * 16 + ((lane >> 4) << 3) + (lane & 7);
                    const int g = 2 * ks + ((lane >> 3) & 1);
                    ldmatrix_x4(kb, sK + n * 128 + ((uint32_t)(g ^ (n & 7)) << 4));
                    mma16816h(S[2 * pp],     qf[ks], kb + 0);
                    mma16816h(S[2 * pp + 1], qf[ks], kb + 2);
                }
            }

            // ---- causal mask ----
            const int r0g = wrow + (lane >> 2);
            const int r1g = r0g + 8;
            if (j64 * 64 + 63 > wrow) {
                #pragma unroll
                for (int nt = 0; nt < 8; nt++) {
                    const int c = j64 * 64 + nt * 8 + 2 * (lane & 3);
                    if (c     > r0g) S[nt][0] = -1e30f;
                    if (c + 1 > r0g) S[nt][1] = -1e30f;
                    if (c     > r1g) S[nt][2] = -1e30f;
                    if (c + 1 > r1g) S[nt][3] = -1e30f;
                }
            }

            // ---- online softmax ----
            float mt0 = -1e30f, mt1 = -1e30f;
            #pragma unroll
            for (int nt = 0; nt < 8; nt++) {
                mt0 = fmaxf(mt0, fmaxf(S[nt][0], S[nt][1]));
                mt1 = fmaxf(mt1, fmaxf(S[nt][2], S[nt][3]));
            }
            mt0 = fmaxf(mt0, __shfl_xor_sync(0xffffffffu, mt0, 1));
            mt0 = fmaxf(mt0, __shfl_xor_sync(0xffffffffu, mt0, 2));
            mt1 = fmaxf(mt1, __shfl_xor_sync(0xffffffffu, mt1, 1));
            mt1 = fmaxf(mt1, __shfl_xor_sync(0xffffffffu, mt1, 2));
            const float mn0 = fmaxf(m0, mt0), mn1 = fmaxf(m1, mt1);
            const float c0 = ex2f((m0 - mn0) * CEXP);
            const float c1 = ex2f((m1 - mn1) * CEXP);
            l0 *= c0; l1 *= c1;
            m0 = mn0; m1 = mn1;
            #pragma unroll
            for (int j = 0; j < 8; j++) {
                O[j][0] *= c0; O[j][1] *= c0;
                O[j][2] *= c1; O[j][3] *= c1;
            }
            #pragma unroll
            for (int nt = 0; nt < 8; nt++) {
                S[nt][0] = ex2f((S[nt][0] - mn0) * CEXP);
                S[nt][1] = ex2f((S[nt][1] - mn0) * CEXP);
                S[nt][2] = ex2f((S[nt][2] - mn1) * CEXP);
                S[nt][3] = ex2f((S[nt][3] - mn1) * CEXP);
                l0 += S[nt][0] + S[nt][1];
                l1 += S[nt][2] + S[nt][3];
            }

            // ---- O += P.Vh, P in plain fp16 ----
            #pragma unroll
            for (int ks2 = 0; ks2 < 4; ks2++) {
                uint32_t ap[4];
                __half2 p0 = __floats2half2_rn(S[2*ks2  ][0], S[2*ks2  ][1]);
                __half2 p1 = __floats2half2_rn(S[2*ks2  ][2], S[2*ks2  ][3]);
                __half2 p2 = __floats2half2_rn(S[2*ks2+1][0], S[2*ks2+1][1]);
                __half2 p3 = __floats2half2_rn(S[2*ks2+1][2], S[2*ks2+1][3]);
                ap[0] = *reinterpret_cast<uint32_t*>(&p0);
                ap[1] = *reinterpret_cast<uint32_t*>(&p1);
                ap[2] = *reinterpret_cast<uint32_t*>(&p2);
                ap[3] = *reinterpret_cast<uint32_t*>(&p3);
                #pragma unroll
                for (int np = 0; np < 4; np++) {
                    const int r = 16 * ks2 + (lane & 15);
                    const int g = 2 * np + (lane >> 4);
                    const uint32_t addr_off = r * 128 + (((g ^ (r & 7)) & 7) << 4);
                    uint32_t bhv[4];
                    ldmatrix_x4t(bhv, sVh + addr_off);
                    mma16816h(O[2*np],     ap, bhv + 0);
                    mma16816h(O[2*np + 1], ap, bhv + 2);
                }
            }
        }

        stage ^= 1;
    }

    // ---- finalize: normalize and write fp16 proj-GEMM input ----
    l0 += __shfl_xor_sync(0xffffffffu, l0, 1);
    l0 += __shfl_xor_sync(0xffffffffu, l0, 2);
    l1 += __shfl_xor_sync(0xffffffffu, l1, 1);
    l1 += __shfl_xor_sync(0xffffffffu, l1, 2);
    const float inv0 = 1.f / l0, inv1 = 1.f / l1;
    const int r0g = wrow + (lane >> 2);
    __half2* a2h = (__half2*)a2out;
    #pragma unroll
    for (int nt = 0; nt < 8; nt++) {
        const int col = h * 64 + nt * 8 + 2 * (lane & 3);
        const size_t row0 = (size_t)(b * SEQ + r0g);
        const size_t row1 = row0 + 8;
        a2h[row0 * 512 + (col >> 1)] = __floats2half2_rn(O[nt][0] * inv0, O[nt][1] * inv0);
        a2h[row1 * 512 + (col >> 1)] = __floats2half2_rn(O[nt][2] * inv1, O[nt][3] * inv1);
    }
}

// ---------------------------------------------------------------------------
// Launch
// ---------------------------------------------------------------------------
extern "C" void kernel_launch(void* const* d_in, const int* in_sizes, int n_in,
                              void* d_out, int out_size)
{
    const float* x      = (const float*)d_in[0];
    const float* W_attn = (const float*)d_in[1];
    const float* b_attn = (const float*)d_in[2];
    const float* W_proj = (const float*)d_in[3];
    const float* b_proj = (const float*)d_in[4];
    float* out = (float*)d_out;

    __half *a2, *w2a, *w2p, *Qp, *Kpq, *Vh;
    cudaGetSymbolAddress((void**)&a2,  g_a2);
    cudaGetSymbolAddress((void**)&w2a, g_w2a);
    cudaGetSymbolAddress((void**)&w2p, g_w2p);
    cudaGetSymbolAddress((void**)&Qp,  g_Qp);
    cudaGetSymbolAddress((void**)&Kpq, g_Kp);
    cudaGetSymbolAddress((void**)&Vh,  g_Vh);

    cudaFuncSetAttribute(gemm_fp16<0>,
                         cudaFuncAttributeMaxDynamicSharedMemorySize, GEMM_SMEM_SZ);
    cudaFuncSetAttribute(gemm_fp16<1>,
                         cudaFuncAttributeMaxDynamicSharedMemorySize, GEMM_SMEM_SZ);
    cudaFuncSetAttribute(flash_attn_tc,
                         cudaFuncAttributeMaxDynamicSharedMemorySize, ATT_SMEM);

    // 0) fused packs (x -> fp16, W_attn^T, W_proj^T) in one launch
    pack_all<<<12288, 256>>>(x, a2, W_attn, w2a, W_proj, w2p);

    // 1) QKV projection + fused scatter into attention operands
    gemm_fp16<1><<<dim3(QKV_N / 128, MROWS / 128), 256, GEMM_SMEM_SZ>>>(
        a2, w2a, b_attn, nullptr, QKV_N,
        (__half2*)Qp, (__half2*)Kpq, (__half2*)Vh);

    // 2) tensor-core flash attention (hoisted Q frags), writes fp16 proj input
    flash_attn_tc<<<dim3(16, BATCH * NHEAD), 256, ATT_SMEM>>>(Qp, Kpq, Vh, a2);

    // 3) output projection
    gemm_fp16<0><<<dim3(EMBD / 128, MROWS / 128), 256, GEMM_SMEM_SZ>>>(
        a2, w2p, b_proj, out, EMBD, nullptr, nullptr, nullptr);
}

// round 17
// speedup vs baseline: 1.0099x; 1.0099x over previous
#include <cuda_runtime.h>
#include <cuda_fp16.h>
#include <cstdint>
#include <math.h>

// Problem constants
#define BATCH   4
#define SEQ     2048
#define EMBD    1024
#define NHEAD   16
#define HDIM    64
#define MROWS   (BATCH * SEQ)        // 8192
#define QKV_N   (3 * EMBD)           // 3072

// ---------------------------------------------------------------------------
// Scratch (device globals: allocation-free per harness rules)
// ---------------------------------------------------------------------------
__device__ __half g_a2 [(size_t)MROWS * EMBD];  // [8192,1024] fp16 (x, then attn-out)
__device__ __half g_w2a[(size_t)QKV_N * EMBD];  // [3072,1024] fp16 W_attn^T
__device__ __half g_w2p[(size_t)EMBD * EMBD];   // [1024,1024] fp16 W_proj^T
// attention operands, head-major (plain fp16)
__device__ __half g_Qp[(size_t)BATCH * NHEAD * SEQ * 64];
__device__ __half g_Kp[(size_t)BATCH * NHEAD * SEQ * 64];
__device__ __half g_Vh[(size_t)BATCH * NHEAD * SEQ * 64];

// ---------------------------------------------------------------------------
// Portable PTX helpers (valid on compute_103)
// ---------------------------------------------------------------------------
__device__ __forceinline__ uint32_t smem_u32(const void* p) {
    uint32_t a;
    asm("{ .reg .u64 t; cvta.to.shared.u64 t, %1; cvt.u32.u64 %0, t; }"
        : "=r"(a) : "l"(p));
    return a;
}
__device__ __forceinline__ void cp_async16(uint32_t dst, const void* src) {
    asm volatile("cp.async.cg.shared.global [%0], [%1], 16;"
                 :: "r"(dst), "l"(src) : "memory");
}
__device__ __forceinline__ void cp_commit() {
    asm volatile("cp.async.commit_group;" ::: "memory");
}
template <int N>
__device__ __forceinline__ void cp_wait() {
    asm volatile("cp.async.wait_group %0;" :: "n"(N) : "memory");
}
__device__ __forceinline__ void ldmatrix_x4(uint32_t* r, uint32_t addr) {
    asm volatile("ldmatrix.sync.aligned.m8n8.x4.shared.b16 {%0,%1,%2,%3}, [%4];"
                 : "=r"(r[0]), "=r"(r[1]), "=r"(r[2]), "=r"(r[3]) : "r"(addr));
}
__device__ __forceinline__ void ldmatrix_x4t(uint32_t* r, uint32_t addr) {
    asm volatile("ldmatrix.sync.aligned.m8n8.x4.trans.shared.b16 {%0,%1,%2,%3}, [%4];"
                 : "=r"(r[0]), "=r"(r[1]), "=r"(r[2]), "=r"(r[3]) : "r"(addr));
}
__device__ __forceinline__ void mma16816h(float* c, const uint32_t* a, const uint32_t* b) {
    asm volatile(
        "mma.sync.aligned.m16n8k16.row.col.f32.f16.f16.f32 "
        "{%0,%1,%2,%3}, {%4,%5,%6,%7}, {%8,%9}, {%0,%1,%2,%3};"
        : "+f"(c[0]), "+f"(c[1]), "+f"(c[2]), "+f"(c[3])
        : "r"(a[0]), "r"(a[1]), "r"(a[2]), "r"(a[3]), "r"(b[0]), "r"(b[1]));
}
__device__ __forceinline__ float ex2f(float x) {
    float r;
    asm("ex2.approx.f32 %0, %1;" : "=f"(r) : "f"(x));
    return r;
}

// ---------------------------------------------------------------------------
// Fused pack kernel (single launch):
//   blocks [0, 2048)         : x fp32 -> a2 fp16 (4 float4 per thread)
//   blocks [2048, 5120)      : W_attn^T pack (96 x 32 tiles)
//   blocks [5120, 6144)      : W_proj^T pack (32 x 32 tiles)
// ---------------------------------------------------------------------------
__global__ __launch_bounds__(256)
void pack_all(const float* __restrict__ x, __half* __restrict__ a2,
              const float* __restrict__ Wa, __half* __restrict__ w2a,
              const float* __restrict__ Wp, __half* __restrict__ w2p)
{
    const int bid = blockIdx.x;
    if (bid < 2048) {
        __half2* d = (__half2*)a2;
        #pragma unroll
        for (int u = 0; u < 4; u++) {
            const int i = (bid * 4 + u) * 256 + threadIdx.x;
            float4 v = ((const float4*)x)[i];
            d[2 * i + 0] = __floats2half2_rn(v.x, v.y);
            d[2 * i + 1] = __floats2half2_rn(v.z, v.w);
        }
        return;
    }
    __shared__ float t[32][33];
    const float* W;
    __half* W2;
    int n0, k0, Nd;
    if (bid < 2048 + 3072) {
        const int tb = bid - 2048;
        W = Wa; W2 = w2a; Nd = QKV_N;
        n0 = (tb % 96) * 32; k0 = (tb / 96) * 32;
    } else {
        const int tb = bid - 5120;
        W = Wp; W2 = w2p; Nd = EMBD;
        n0 = (tb % 32) * 32; k0 = (tb / 32) * 32;
    }
    const int tx = threadIdx.x & 31;
    const int ty = threadIdx.x >> 5;
    #pragma unroll
    for (int i = 0; i < 32; i += 8)
        t[ty + i][tx] = W[(size_t)(k0 + ty + i) * Nd + n0 + tx];
    __syncthreads();
    #pragma unroll
    for (int i = 0; i < 32; i += 8)
        W2[(size_t)(n0 + ty + i) * EMBD + k0 + tx] = __float2half_rn(t[tx][ty + i]);
}

// ---------------------------------------------------------------------------
// fp16 tensor-core GEMM (exact R12 config — best measured).
// ---------------------------------------------------------------------------
#define STAGE_SZ     32768               // A 16KB + B 16KB
#define GEMM_SMEM_SZ (3 * STAGE_SZ)      // 98304

__device__ __forceinline__ void load_stage(uint32_t st,
                                           const __half* A, const __half* B,
                                           int bm, int bn, int kc, int tid)
{
    const size_t ko = (size_t)kc * 64;
    const uint32_t sA = st, sB = st + 16384;
    #pragma unroll
    for (int i = 0; i < 4; i++) {
        const int idx = tid + i * 256;
        const int r = idx >> 3;
        const int g = idx & 7;
        const uint32_t so = (uint32_t)r * 128 + (uint32_t)((g ^ (r & 7)) << 4);
        cp_async16(sA + so, (const char*)(A + (size_t)(bm + r) * EMBD + ko) + g * 16);
        cp_async16(sB + so, (const char*)(B + (size_t)(bn + r) * EMBD + ko) + g * 16);
    }
}

template <int MODE>
__global__ __launch_bounds__(256, 2)
void gemm_fp16(const __half* __restrict__ A2, const __half* __restrict__ W2,
               const float* __restrict__ bias, float* __restrict__ C, int N,
               __half2* __restrict__ Qp, __half2* __restrict__ Kp,
               __half2* __restrict__ Vh)
{
    extern __shared__ char dsm[];
    const int tid  = threadIdx.x;
    const int lane = tid & 31;
    const int wid  = tid >> 5;
    const int wm   = wid >> 2;
    const int wn   = wid & 3;
    const int bm   = blockIdx.y * 128;
    const int bn   = blockIdx.x * 128;

    const uint32_t sbase = smem_u32(dsm);
    float acc[4][4][4];
    #pragma unroll
    for (int mt = 0; mt < 4; mt++)
        #pragma unroll
        for (int nt = 0; nt < 4; nt++)
            #pragma unroll
            for (int j = 0; j < 4; j++) acc[mt][nt][j] = 0.f;

    const int NK = EMBD / 64;   // 16

    load_stage(sbase,            A2, W2, bm, bn, 0, tid);
    cp_commit();
    load_stage(sbase + STAGE_SZ, A2, W2, bm, bn, 1, tid);
    cp_commit();

    uint32_t stage = 0;
    for (int kc = 0; kc < NK; kc++) {
        if (kc == NK - 1) cp_wait<0>(); else cp_wait<1>();
        __syncthreads();
        if (kc + 2 < NK) {
            uint32_t nb = stage + 2;
            if (nb >= 3) nb -= 3;
            load_stage(sbase + nb * STAGE_SZ, A2, W2, bm, bn, kc + 2, tid);
            cp_commit();
        }

        const uint32_t sA = sbase + stage * STAGE_SZ;
        const uint32_t sB = sA + 16384;
        if (++stage == 3) stage = 0;

        #pragma unroll
        for (int ks = 0; ks < 4; ks++) {
            uint32_t a[4][4], bb[2][4];
            #pragma unroll
            for (int mt = 0; mt < 4; mt++) {
                const int r = wm * 64 + mt * 16 + (lane & 15);
                const int g = ks * 2 + (lane >> 4);
                ldmatrix_x4(a[mt], sA + r * 128 + ((g ^ (r & 7)) << 4));
            }
            #pragma unroll
            for (int pp = 0; pp < 2; pp++) {
                const int n = wn * 32 + pp * 16 + ((lane >> 4) << 3) + (lane & 7);
                const int g = ks * 2 + ((lane >> 3) & 1);
                ldmatrix_x4(bb[pp], sB + n * 128 + ((g ^ (n & 7)) << 4));
            }
            #pragma unroll
            for (int mt = 0; mt < 4; mt++) {
                mma16816h(acc[mt][0], a[mt], bb[0] + 0);
                mma16816h(acc[mt][1], a[mt], bb[0] + 2);
                mma16816h(acc[mt][2], a[mt], bb[1] + 0);
                mma16816h(acc[mt][3], a[mt], bb[1] + 2);
            }
        }
    }
    __syncthreads();

    #pragma unroll
    for (int mt = 0; mt < 4; mt++) {
        const int r0 = bm + wm * 64 + mt * 16 + (lane >> 2);
        #pragma unroll
        for (int nt = 0; nt < 4; nt++) {
            const int c0 = bn + wn * 32 + nt * 8 + 2 * (lane & 3);
            const float b0 = bias[c0], b1 = bias[c0 + 1];
            float2 v0 = make_float2(acc[mt][nt][0] + b0, acc[mt][nt][1] + b1);
            float2 v1 = make_float2(acc[mt][nt][2] + b0, acc[mt][nt][3] + b1);
            if (MODE == 0) {
                *(float2*)&C[(size_t)r0 * N + c0]       = v0;
                *(float2*)&C[(size_t)(r0 + 8) * N + c0] = v1;
            } else {
                #pragma unroll
                for (int half_row = 0; half_row < 2; half_row++) {
                    const int row = r0 + half_row * 8;
                    const float2 v = half_row ? v1 : v0;
                    const int bb2 = row >> 11;
                    const int t   = row & 2047;
                    const int reg = c0 >> 10;        // 0=q 1=k 2=v
                    const int cc  = c0 & 1023;
                    const int h   = cc >> 6;
                    const int d2  = (cc & 63) >> 1;
                    const size_t ob = ((size_t)(bb2 * NHEAD + h) * SEQ + t);
                    const __half2 hv = __floats2half2_rn(v.x, v.y);
                    if (reg == 0)      Qp[ob * 32 + d2] = hv;
                    else if (reg == 1) Kp[ob * 32 + d2] = hv;
                    else               Vh[ob * 32 + d2] = hv;
                }
            }
        }
    }
}

// ---------------------------------------------------------------------------
// Tensor-core causal flash attention (plain fp16 Q/K/V) — exact R15 config.
// 8 warps x 16 rows, 128-KEY load tiles processed as two 64-key halves.
// 2-stage KV ring, ONE barrier per 128-key tile.
// SMEM: Q [128][128B] + 2 x (K 16KB + V 16KB) = 80KB -> 2 CTAs/SM.
// ---------------------------------------------------------------------------
#define KV_STAGE 32768                    // K 16KB + V 16KB (128 rows each)
#define ATT_SMEM (16384 + 2 * KV_STAGE)   // 81920
#define CEXP 0.18033688f   // 0.125 * log2(e)

__global__ __launch_bounds__(256, 2)
void flash_attn_tc(const __half* __restrict__ Qp, const __half* __restrict__ Kpp,
                   const __half* __restrict__ Vh, __half* __restrict__ a2out)
{
    extern __shared__ char dsm[];
    const uint32_t sQ  = smem_u32(dsm);
    const uint32_t sKV = sQ + 16384;

    const int qt   = 15 - blockIdx.x;      // heavy tiles first
    const int bh   = blockIdx.y;
    const int b    = bh >> 4;
    const int h    = bh & 15;
    const int tid  = threadIdx.x;
    const int lane = tid & 31;
    const int w    = tid >> 5;
    const int qr0  = qt * 128;

    const __half* Kg  = Kpp + (size_t)bh * SEQ * 64;
    const __half* VhG = Vh  + (size_t)bh * SEQ * 64;

    // ---- load Q tile (resident): 128 rows x 128B ----
    const __half* Qg = Qp + ((size_t)bh * SEQ + qr0) * 64;
    #pragma unroll
    for (int i = 0; i < 4; i++) {
        const int idx = tid + i * 256;     // 0..1023
        const int r = idx >> 3;
        const int g = idx & 7;
        const uint32_t sw = (uint32_t)((g ^ (r & 7)) << 4);
        cp_async16(sQ + r * 128 + sw, Qg + (size_t)r * 64 + g * 8);
    }
    cp_commit();

    // 128-key tile loader (K and V, 128 rows x 128B each)
    auto load_kv = [&](int s, int kt) {
        const __half* kg  = Kg  + (size_t)(kt * 128) * 64;
        const __half* vhg = VhG + (size_t)(kt * 128) * 64;
        const uint32_t sK  = sKV + (uint32_t)s * KV_STAGE;
        const uint32_t sV  = sK + 16384;
        #pragma unroll
        for (int i = 0; i < 4; i++) {
            const int f = tid + i * 256;   // 0..1023
            const int r = f >> 3;
            const int g = f & 7;
            const uint32_t sw = (uint32_t)((g ^ (r & 7)) << 4);
            cp_async16(sK + r * 128 + sw, kg  + (size_t)r * 64 + g * 8);
            cp_async16(sV + r * 128 + sw, vhg + (size_t)r * 64 + g * 8);
        }
    };

    const int nkt = qt + 1;                // 128-key tiles

    load_kv(0, 0);
    cp_commit();

    float O[8][4];
    #pragma unroll
    for (int j = 0; j < 8; j++)
        #pragma unroll
        for (int i = 0; i < 4; i++) O[j][i] = 0.f;
    float m0 = -1e30f, m1 = -1e30f, l0 = 0.f, l1 = 0.f;

    const int wrow = qr0 + w * 16;
    const int kt_max_w = (wrow + 15) >> 6;   // in 64-key units

    int stage = 0;
    for (int kt = 0; kt < nkt; kt++) {
        cp_wait<0>();      // tile kt (and Q on kt==0) fully in smem
        __syncthreads();   // all warps finished compute of tile kt-1

        // prefetch tile kt+1 into the stage drained at kt-1 (safe post-barrier)
        if (kt + 1 < nkt) {
            load_kv(stage ^ 1, kt + 1);
            cp_commit();
        }

        // two 64-key halves within the 128-key tile
        #pragma unroll
        for (int hv2 = 0; hv2 < 2; hv2++) {
            const int j64 = 2 * kt + hv2;       // 64-key tile index
            if (j64 > kt_max_w) break;
            const uint32_t sK  = sKV + (uint32_t)stage * KV_STAGE + hv2 * 8192;
            const uint32_t sVh = sKV + (uint32_t)stage * KV_STAGE + 16384 + hv2 * 8192;

            // ---- S = Q.K^T ----
            float S[8][4];
            #pragma unroll
            for (int j = 0; j < 8; j++)
                #pragma unroll
                for (int i = 0; i < 4; i++) S[j][i] = 0.f;

            #pragma unroll
            for (int ks = 0; ks < 4; ks++) {
                uint32_t qf[4];
                {
                    const int r = w * 16 + (lane & 15);
                    const int g = 2 * ks + (lane >> 4);
                    ldmatrix_x4(qf, sQ + r * 128 + ((uint32_t)(g ^ (r & 7)) << 4));
                }
                #pragma unroll
                for (int pp = 0; pp < 4; pp++) {
                    uint32_t kb[4];
                    const int n = pp * 16 + ((lane >> 4) << 3) + (lane & 7);
                    const int g = 2 * ks + ((lane >> 3) & 1);
                    ldmatrix_x4(kb, sK + n * 128 + ((uint32_t)(g ^ (n & 7)) << 4));
                    mma16816h(S[2 * pp],     qf, kb + 0);
                    mma16816h(S[2 * pp + 1], qf, kb + 2);
                }
            }

            // ---- causal mask ----
            const int r0g = wrow + (lane >> 2);
            const int r1g = r0g + 8;
            if (j64 * 64 + 63 > wrow) {
                #pragma unroll
                for (int nt = 0; nt < 8; nt++) {
                    const int c = j64 * 64 + nt * 8 + 2 * (lane & 3);
                    if (c     > r0g) S[nt][0] = -1e30f;
                    if (c + 1 > r0g) S[nt][1] = -1e30f;
                    if (c     > r1g) S[nt][2] = -1e30f;
                    if (c + 1 > r1g) S[nt][3] = -1e30f;
                }
            }

            // ---- online softmax ----
            float mt0 = -1e30f, mt1 = -1e30f;
            #pragma unroll
            for (int nt = 0; nt < 8; nt++) {
                mt0 = fmaxf(mt0, fmaxf(S[nt][0], S[nt][1]));
                mt1 = fmaxf(mt1, fmaxf(S[nt][2], S[nt][3]));
            }
            mt0 = fmaxf(mt0, __shfl_xor_sync(0xffffffffu, mt0, 1));
            mt0 = fmaxf(mt0, __shfl_xor_sync(0xffffffffu, mt0, 2));
            mt1 = fmaxf(mt1, __shfl_xor_sync(0xffffffffu, mt1, 1));
            mt1 = fmaxf(mt1, __shfl_xor_sync(0xffffffffu, mt1, 2));
            const float mn0 = fmaxf(m0, mt0), mn1 = fmaxf(m1, mt1);
            const float c0 = ex2f((m0 - mn0) * CEXP);
            const float c1 = ex2f((m1 - mn1) * CEXP);
            l0 *= c0; l1 *= c1;
            m0 = mn0; m1 = mn1;
            #pragma unroll
            for (int j = 0; j < 8; j++) {
                O[j][0] *= c0; O[j][1] *= c0;
                O[j][2] *= c1; O[j][3] *= c1;
            }
            #pragma unroll
            for (int nt = 0; nt < 8; nt++) {
                S[nt][0] = ex2f((S[nt][0] - mn0) * CEXP);
                S[nt][1] = ex2f((S[nt][1] - mn0) * CEXP);
                S[nt][2] = ex2f((S[nt][2] - mn1) * CEXP);
                S[nt][3] = ex2f((S[nt][3] - mn1) * CEXP);
                l0 += S[nt][0] + S[nt][1];
                l1 += S[nt][2] + S[nt][3];
            }

            // ---- O += P.Vh, P in plain fp16 ----
            #pragma unroll
            for (int ks2 = 0; ks2 < 4; ks2++) {
                uint32_t ap[4];
                __half2 p0 = __floats2half2_rn(S[2*ks2  ][0], S[2*ks2  ][1]);
                __half2 p1 = __floats2half2_rn(S[2*ks2  ][2], S[2*ks2  ][3]);
                __half2 p2 = __floats2half2_rn(S[2*ks2+1][0], S[2*ks2+1][1]);
                __half2 p3 = __floats2half2_rn(S[2*ks2+1][2], S[2*ks2+1][3]);
                ap[0] = *reinterpret_cast<uint32_t*>(&p0);
                ap[1] = *reinterpret_cast<uint32_t*>(&p1);
                ap[2] = *reinterpret_cast<uint32_t*>(&p2);
                ap[3] = *reinterpret_cast<uint32_t*>(&p3);
                #pragma unroll
                for (int np = 0; np < 4; np++) {
                    const int r = 16 * ks2 + (lane & 15);
                    const int g = 2 * np + (lane >> 4);
                    const uint32_t addr_off = r * 128 + (((g ^ (r & 7)) & 7) << 4);
                    uint32_t bhv[4];
                    ldmatrix_x4t(bhv, sVh + addr_off);
                    mma16816h(O[2*np],     ap, bhv + 0);
                    mma16816h(O[2*np + 1], ap, bhv + 2);
                }
            }
        }

        stage ^= 1;
    }

    // ---- finalize: normalize and write fp16 proj-GEMM input ----
    l0 += __shfl_xor_sync(0xffffffffu, l0, 1);
    l0 += __shfl_xor_sync(0xffffffffu, l0, 2);
    l1 += __shfl_xor_sync(0xffffffffu, l1, 1);
    l1 += __shfl_xor_sync(0xffffffffu, l1, 2);
    const float inv0 = 1.f / l0, inv1 = 1.f / l1;
    const int r0g = wrow + (lane >> 2);
    __half2* a2h = (__half2*)a2out;
    #pragma unroll
    for (int nt = 0; nt < 8; nt++) {
        const int col = h * 64 + nt * 8 + 2 * (lane & 3);
        const size_t row0 = (size_t)(b * SEQ + r0g);
        const size_t row1 = row0 + 8;
        a2h[row0 * 512 + (col >> 1)] = __floats2half2_rn(O[nt][0] * inv0, O[nt][1] * inv0);
        a2h[row1 * 512 + (col >> 1)] = __floats2half2_rn(O[nt][2] * inv1, O[nt][3] * inv1);
    }
}

// ---------------------------------------------------------------------------
// Launch
// ---------------------------------------------------------------------------
extern "C" void kernel_launch(void* const* d_in, const int* in_sizes, int n_in,
                              void* d_out, int out_size)
{
    const float* x      = (const float*)d_in[0];
    const float* W_attn = (const float*)d_in[1];
    const float* b_attn = (const float*)d_in[2];
    const float* W_proj = (const float*)d_in[3];
    const float* b_proj = (const float*)d_in[4];
    float* out = (float*)d_out;

    __half *a2, *w2a, *w2p, *Qp, *Kpq, *Vh;
    cudaGetSymbolAddress((void**)&a2,  g_a2);
    cudaGetSymbolAddress((void**)&w2a, g_w2a);
    cudaGetSymbolAddress((void**)&w2p, g_w2p);
    cudaGetSymbolAddress((void**)&Qp,  g_Qp);
    cudaGetSymbolAddress((void**)&Kpq, g_Kp);
    cudaGetSymbolAddress((void**)&Vh,  g_Vh);

    cudaFuncSetAttribute(gemm_fp16<0>,
                         cudaFuncAttributeMaxDynamicSharedMemorySize, GEMM_SMEM_SZ);
    cudaFuncSetAttribute(gemm_fp16<1>,
                         cudaFuncAttributeMaxDynamicSharedMemorySize, GEMM_SMEM_SZ);
    cudaFuncSetAttribute(flash_attn_tc,
                         cudaFuncAttributeMaxDynamicSharedMemorySize, ATT_SMEM);

    // 0) fused packs (x -> fp16, W_attn^T, W_proj^T) in one launch
    pack_all<<<6144, 256>>>(x, a2, W_attn, w2a, W_proj, w2p);

    // 1) QKV projection + fused scatter into attention operands
    gemm_fp16<1><<<dim3(QKV_N / 128, MROWS / 128), 256, GEMM_SMEM_SZ>>>(
        a2, w2a, b_attn, nullptr, QKV_N,
        (__half2*)Qp, (__half2*)Kpq, (__half2*)Vh);

    // 2) tensor-core flash attention (R15 config), writes fp16 proj input
    flash_attn_tc<<<dim3(16, BATCH * NHEAD), 256, ATT_SMEM>>>(Qp, Kpq, Vh, a2);

    // 3) output projection
    gemm_fp16<0><<<dim3(EMBD / 128, MROWS / 128), 256, GEMM_SMEM_SZ>>>(
        a2, w2p, b_proj, out, EMBD, nullptr, nullptr, nullptr);
}